// round 2
// baseline (speedup 1.0000x reference)
#include <cuda_runtime.h>
#include <cstdint>

// ---------------------------------------------------------------------------
// Network_28054726377822 : LSTM  B=64, T=1024, D=512, U=512, OUT=4
//   1) xz[b,t,:] = tx[b,t,:] @ kernel + bias        (parallel SGEMM, f32x2)
//   2) 1024 sequential steps (persistent grid-synced kernel):
//        z = xz_t + h @ R ; gates ; c,h update
//   3) out = softmax(h_last @ fc_w + fc_b)
// ---------------------------------------------------------------------------

#define BATCH    64
#define TSTEPS   1024
#define DIN      512
#define UNITS    512
#define FOURU    2048
#define NCTA_REC 128

// -------- device scratch (allocation-free per harness rules) ---------------
__device__ float             g_xz[(size_t)BATCH * TSTEPS * FOURU]; // 512 MB
__device__ float             g_h[2][UNITS][BATCH];                 // hT[par][k][b]
__device__ unsigned          g_arrive;
__device__ volatile unsigned g_gen;

// -------- packed f32x2 helpers ---------------------------------------------
typedef unsigned long long u64t;
__device__ __forceinline__ u64t splat2(float x) {
    u64t r; asm("mov.b64 %0, {%1, %1};" : "=l"(r) : "f"(x)); return r;
}
__device__ __forceinline__ void ffma2(u64t& d, u64t a, u64t b) {
    asm("fma.rn.f32x2 %0, %1, %2, %0;" : "+l"(d) : "l"(a), "l"(b));
}
__device__ __forceinline__ float2 unpack2(u64t v) {
    float2 f; asm("mov.b64 {%0, %1}, %2;" : "=f"(f.x), "=f"(f.y) : "l"(v)); return f;
}
__device__ __forceinline__ float fsig(float x) {
    return __fdividef(1.f, 1.f + __expf(-x));
}

// -------- init: zero h0 buffers + barrier state ----------------------------
__global__ void init_kernel() {
    int i = blockIdx.x * blockDim.x + threadIdx.x;
    if (i < 2 * UNITS * BATCH) ((float*)g_h)[i] = 0.f;
    if (i == 0) { g_arrive = 0u; g_gen = 0u; }
}

// -------- input GEMM: g_xz[65536,2048] = A[65536,512] @ W[512,2048] + bias -
// 128x128 CTA tile, BK=8, 256 threads, 8x8 microtile, f32x2 accumulators.
__global__ __launch_bounds__(256) void sgemm_bias(
    const float* __restrict__ A, const float* __restrict__ W,
    const float* __restrict__ bias)
{
    __shared__ float As[8][128];
    __shared__ float Bs[8][128];

    const int tid = threadIdx.x;
    const int tx = tid & 15, ty = tid >> 4;
    const int bx = blockIdx.x, by = blockIdx.y;

    const int aRow = tid >> 1, aK = (tid & 1) * 4;
    const int wK = tid >> 5, wN = (tid & 31) * 4;

    const float* Aptr = A + (size_t)(by * 128 + aRow) * DIN + aK;
    const float* Wptr = W + (size_t)wK * FOURU + bx * 128 + wN;

    float4 aReg = *(const float4*)Aptr;
    float4 wReg = *(const float4*)Wptr;

    u64t acc[8][4];
#pragma unroll
    for (int m = 0; m < 8; m++)
#pragma unroll
        for (int n = 0; n < 4; n++) acc[m][n] = 0ull;

    for (int kt = 0; kt < DIN / 8; kt++) {
        As[aK + 0][aRow] = aReg.x;
        As[aK + 1][aRow] = aReg.y;
        As[aK + 2][aRow] = aReg.z;
        As[aK + 3][aRow] = aReg.w;
        *(float4*)&Bs[wK][wN] = wReg;
        __syncthreads();

        if (kt < DIN / 8 - 1) {
            aReg = *(const float4*)(Aptr + (kt + 1) * 8);
            wReg = *(const float4*)(Wptr + (size_t)(kt + 1) * 8 * FOURU);
        }

#pragma unroll
        for (int k = 0; k < 8; k++) {
            float4 a0 = *(const float4*)&As[k][ty * 8];
            float4 a1 = *(const float4*)&As[k][ty * 8 + 4];
            ulonglong2 b01 = *(const ulonglong2*)&Bs[k][tx * 8];
            ulonglong2 b23 = *(const ulonglong2*)&Bs[k][tx * 8 + 4];
            float av[8] = {a0.x, a0.y, a0.z, a0.w, a1.x, a1.y, a1.z, a1.w};
#pragma unroll
            for (int m = 0; m < 8; m++) {
                u64t s = splat2(av[m]);
                ffma2(acc[m][0], b01.x, s);
                ffma2(acc[m][1], b01.y, s);
                ffma2(acc[m][2], b23.x, s);
                ffma2(acc[m][3], b23.y, s);
            }
        }
        __syncthreads();
    }

    float4 bias0 = *(const float4*)&bias[bx * 128 + tx * 8];
    float4 bias1 = *(const float4*)&bias[bx * 128 + tx * 8 + 4];
#pragma unroll
    for (int m = 0; m < 8; m++) {
        float* Cp = g_xz + (size_t)(by * 128 + ty * 8 + m) * FOURU + bx * 128 + tx * 8;
        float2 p0 = unpack2(acc[m][0]);
        float2 p1 = unpack2(acc[m][1]);
        float2 p2 = unpack2(acc[m][2]);
        float2 p3 = unpack2(acc[m][3]);
        float4 o0 = make_float4(p0.x + bias0.x, p0.y + bias0.y,
                                p1.x + bias0.z, p1.y + bias0.w);
        float4 o1 = make_float4(p2.x + bias1.x, p2.y + bias1.y,
                                p3.x + bias1.z, p3.y + bias1.w);
        *(float4*)Cp = o0;
        *(float4*)(Cp + 4) = o1;
    }
}

// -------- persistent LSTM recurrence ---------------------------------------
// 128 CTAs x 256 threads, all co-resident. CTA owns units [4*cta,4*cta+4):
// R slice [512][16] in SMEM ordered [k][unit*4+gate]. Thread <-> (batch,unit)
// bijection: warp w, lane l -> b = 8w+(l&7), j = l>>3. Each lane keeps its 4
// gate dot-products in 2 f32x2 accumulators and its c state in a register for
// all 1024 steps. h exchanged transposed, double-buffered, via L2 (ldcg/stcg).
__global__ __launch_bounds__(256, 1) void lstm_recur(const float* __restrict__ R)
{
    __shared__ float R_s[DIN][16];

    const int tid = threadIdx.x;
    const int w = tid >> 5, l = tid & 31;
    const int u0 = blockIdx.x * 4;

    // R_s[k][j*4+g] = R[k][g*512 + u0 + j]
    for (int i = tid; i < DIN * 16; i += 256) {
        int k = i >> 4, c = i & 15, j = c >> 2, g = c & 3;
        R_s[k][c] = R[(size_t)k * FOURU + g * UNITS + u0 + j];
    }
    __syncthreads();

    const int b = (w << 3) | (l & 7);
    const int j = l >> 3;
    const int u = u0 + j;

    float c_state = 0.f;
    const float* xz_base = g_xz + (size_t)b * TSTEPS * FOURU + u;

    for (int t = 0; t < TSTEPS; t++) {
        // prefetch this thread's 4 gate biases from xz (hidden under GEMM)
        const float* xp = xz_base + (size_t)t * FOURU;
        float x0 = __ldcs(xp);
        float x1 = __ldcs(xp + 512);
        float x2 = __ldcs(xp + 1024);
        float x3 = __ldcs(xp + 1536);

        const float* hb = &g_h[t & 1][0][0];
        u64t acc0 = 0ull, acc1 = 0ull;
#pragma unroll 8
        for (int k = 0; k < DIN; k++) {
            float hv = __ldcg(hb + k * BATCH + b);
            u64t s = splat2(hv);
            ulonglong2 r = *(const ulonglong2*)&R_s[k][j * 4];
            ffma2(acc0, r.x, s);
            ffma2(acc1, r.y, s);
        }

        float2 z01 = unpack2(acc0);
        float2 z23 = unpack2(acc1);
        float z1 = z01.x + x0;
        float z2 = z01.y + x1;
        float z3 = z23.x + x2;
        float z4 = z23.y + x3;

        float v1 = tanhf(z1);
        float v2 = fsig(z2);
        float v3 = fsig(z3);
        float v4 = fsig(z4);
        c_state = v1 * v2 + v3 * c_state;
        float hnew = v4 * tanhf(c_state);

        __stcg(&g_h[(t + 1) & 1][u][b], hnew);

        // ---- grid barrier (sense via generation counter) ----
        __threadfence();
        __syncthreads();
        if (tid == 0) {
            unsigned prev = atomicAdd(&g_arrive, 1u);
            if (prev == NCTA_REC - 1) {
                atomicExch(&g_arrive, 0u);
                __threadfence();
                g_gen = (unsigned)(t + 1);
            } else {
                while (g_gen <= (unsigned)t) { }
            }
        }
        __syncthreads();
    }
}

// -------- final dense + softmax: one warp per batch -------------------------
__global__ void fc_softmax(const float* __restrict__ fc_w,
                           const float* __restrict__ fc_b,
                           float* __restrict__ out)
{
    const int b = blockIdx.x;
    const int l = threadIdx.x;   // 32 threads
    float a0 = 0.f, a1 = 0.f, a2 = 0.f, a3 = 0.f;
    for (int k = l; k < UNITS; k += 32) {
        float h = g_h[0][k][b];   // t=1023 wrote buffer (1023+1)&1 = 0
        const float4 wv = *(const float4*)&fc_w[k * 4];
        a0 += h * wv.x; a1 += h * wv.y; a2 += h * wv.z; a3 += h * wv.w;
    }
#pragma unroll
    for (int o = 16; o > 0; o >>= 1) {
        a0 += __shfl_down_sync(0xffffffffu, a0, o);
        a1 += __shfl_down_sync(0xffffffffu, a1, o);
        a2 += __shfl_down_sync(0xffffffffu, a2, o);
        a3 += __shfl_down_sync(0xffffffffu, a3, o);
    }
    if (l == 0) {
        float z0 = a0 + fc_b[0], z1 = a1 + fc_b[1];
        float z2 = a2 + fc_b[2], z3 = a3 + fc_b[3];
        float m = fmaxf(fmaxf(z0, z1), fmaxf(z2, z3));
        float e0 = __expf(z0 - m), e1 = __expf(z1 - m);
        float e2 = __expf(z2 - m), e3 = __expf(z3 - m);
        float inv = __fdividef(1.f, e0 + e1 + e2 + e3);
        out[b * 4 + 0] = e0 * inv;
        out[b * 4 + 1] = e1 * inv;
        out[b * 4 + 2] = e2 * inv;
        out[b * 4 + 3] = e3 * inv;
    }
}

// ---------------------------------------------------------------------------
extern "C" void kernel_launch(void* const* d_in, const int* in_sizes, int n_in,
                              void* d_out, int out_size)
{
    const float* tx      = (const float*)d_in[0];  // [64,1024,512]
    const float* kernelW = (const float*)d_in[1];  // [512,2048]
    const float* R       = (const float*)d_in[2];  // [512,2048]
    const float* bias    = (const float*)d_in[3];  // [2048]
    const float* fc_w    = (const float*)d_in[4];  // [512,4]
    const float* fc_b    = (const float*)d_in[5];  // [4]
    float* out           = (float*)d_out;          // [64,4]

    init_kernel<<<(2 * UNITS * BATCH + 255) / 256, 256>>>();
    sgemm_bias<<<dim3(FOURU / 128, (BATCH * TSTEPS) / 128), 256>>>(tx, kernelW, bias);
    lstm_recur<<<NCTA_REC, 256>>>(R);
    fc_softmax<<<BATCH, 32>>>(fc_w, fc_b, out);
    (void)in_sizes; (void)n_in; (void)out_size;
}

// round 3
// speedup vs baseline: 1.7046x; 1.7046x over previous
#include <cuda_runtime.h>
#include <cstdint>

// ---------------------------------------------------------------------------
// Network_28054726377822 : LSTM  B=64, T=1024, D=512, U=512, OUT=4
//  1) xz = tx @ kernel + bias              (f32x2 SGEMM)
//  2) 1024 sequential steps, persistent kernel, 128 CTAs:
//       CTA = (unit-group of 16) x (batch-group of 16)
//       R slice in SMEM (128 KB), h staged via SMEM, f32x2 SIMD over k,
//       per-batch-group grid barrier (4 groups x 32 CTAs)
//  3) out = softmax(h_last @ fc_w + fc_b)
// ---------------------------------------------------------------------------

#define BATCH    64
#define TSTEPS   1024
#define DIN      512
#define UNITS    512
#define FOURU    2048
#define NCTA     128
#define TPB      256
#define NBG      4
#define GROUP_CTAS 32

// smem layout (floats)
#define SM_R4    0          // [128 kq][16 u][16 e]   e = g*4+kl : 32768
#define SM_H4    32768      // [128 kq][16 b][4 kl]              : 8192
#define SM_XZ    40960      // [2 buf][4 g][16 u][16 b]          : 2048
#define SM_FLOATS 43008
#define SM_BYTES (SM_FLOATS * 4)

// -------- device scratch ----------------------------------------------------
__device__ float             g_xz[(size_t)BATCH * TSTEPS * FOURU];  // 512 MB
__device__ float             g_h[2][UNITS][BATCH];                  // hT[par][k][b]
__device__ unsigned          g_arrive[NBG * 32];                    // padded
__device__ volatile unsigned g_gen[NBG * 32];                       // padded

// -------- packed f32x2 helpers ---------------------------------------------
typedef unsigned long long u64t;
__device__ __forceinline__ u64t splat2(float x) {
    u64t r; asm("mov.b64 %0, {%1, %1};" : "=l"(r) : "f"(x)); return r;
}
__device__ __forceinline__ void ffma2(u64t& d, u64t a, u64t b) {
    asm("fma.rn.f32x2 %0, %1, %2, %0;" : "+l"(d) : "l"(a), "l"(b));
}
__device__ __forceinline__ float2 unpack2(u64t v) {
    float2 f; asm("mov.b64 {%0, %1}, %2;" : "=f"(f.x), "=f"(f.y) : "l"(v)); return f;
}
__device__ __forceinline__ float fsig(float x) {
    return __fdividef(1.f, 1.f + __expf(-x));
}
__device__ __forceinline__ float ftanh(float x) {
    return 1.f - __fdividef(2.f, __expf(2.f * x) + 1.f);
}

// -------- init --------------------------------------------------------------
__global__ void init_kernel() {
    int i = blockIdx.x * blockDim.x + threadIdx.x;
    if (i < 2 * UNITS * BATCH) ((float*)g_h)[i] = 0.f;
    if (i < NBG * 32) { g_arrive[i] = 0u; g_gen[i] = 0u; }
}

// -------- input GEMM: g_xz[65536,2048] = A[65536,512] @ W[512,2048] + bias --
__global__ __launch_bounds__(256) void sgemm_bias(
    const float* __restrict__ A, const float* __restrict__ W,
    const float* __restrict__ bias)
{
    __shared__ float As[8][128];
    __shared__ float Bs[8][128];

    const int tid = threadIdx.x;
    const int tx = tid & 15, ty = tid >> 4;
    const int bx = blockIdx.x, by = blockIdx.y;

    const int aRow = tid >> 1, aK = (tid & 1) * 4;
    const int wK = tid >> 5, wN = (tid & 31) * 4;

    const float* Aptr = A + (size_t)(by * 128 + aRow) * DIN + aK;
    const float* Wptr = W + (size_t)wK * FOURU + bx * 128 + wN;

    float4 aReg = *(const float4*)Aptr;
    float4 wReg = *(const float4*)Wptr;

    u64t acc[8][4];
#pragma unroll
    for (int m = 0; m < 8; m++)
#pragma unroll
        for (int n = 0; n < 4; n++) acc[m][n] = 0ull;

    for (int kt = 0; kt < DIN / 8; kt++) {
        As[aK + 0][aRow] = aReg.x;
        As[aK + 1][aRow] = aReg.y;
        As[aK + 2][aRow] = aReg.z;
        As[aK + 3][aRow] = aReg.w;
        *(float4*)&Bs[wK][wN] = wReg;
        __syncthreads();

        if (kt < DIN / 8 - 1) {
            aReg = *(const float4*)(Aptr + (kt + 1) * 8);
            wReg = *(const float4*)(Wptr + (size_t)(kt + 1) * 8 * FOURU);
        }

#pragma unroll
        for (int k = 0; k < 8; k++) {
            float4 a0 = *(const float4*)&As[k][ty * 8];
            float4 a1 = *(const float4*)&As[k][ty * 8 + 4];
            ulonglong2 b01 = *(const ulonglong2*)&Bs[k][tx * 8];
            ulonglong2 b23 = *(const ulonglong2*)&Bs[k][tx * 8 + 4];
            float av[8] = {a0.x, a0.y, a0.z, a0.w, a1.x, a1.y, a1.z, a1.w};
#pragma unroll
            for (int m = 0; m < 8; m++) {
                u64t s = splat2(av[m]);
                ffma2(acc[m][0], b01.x, s);
                ffma2(acc[m][1], b01.y, s);
                ffma2(acc[m][2], b23.x, s);
                ffma2(acc[m][3], b23.y, s);
            }
        }
        __syncthreads();
    }

    float4 bias0 = *(const float4*)&bias[bx * 128 + tx * 8];
    float4 bias1 = *(const float4*)&bias[bx * 128 + tx * 8 + 4];
#pragma unroll
    for (int m = 0; m < 8; m++) {
        float* Cp = g_xz + (size_t)(by * 128 + ty * 8 + m) * FOURU + bx * 128 + tx * 8;
        float2 p0 = unpack2(acc[m][0]);
        float2 p1 = unpack2(acc[m][1]);
        float2 p2 = unpack2(acc[m][2]);
        float2 p3 = unpack2(acc[m][3]);
        float4 o0 = make_float4(p0.x + bias0.x, p0.y + bias0.y,
                                p1.x + bias0.z, p1.y + bias0.w);
        float4 o1 = make_float4(p2.x + bias1.x, p2.y + bias1.y,
                                p3.x + bias1.z, p3.y + bias1.w);
        __stcs((float4*)Cp, o0);            // streaming: xz read exactly once later
        __stcs((float4*)(Cp + 4), o1);
    }
}

// -------- persistent LSTM recurrence ---------------------------------------
// CTA (ug, bg): units [16*ug, 16*ug+16), batches [16*bg, 16*bg+16).
// Thread: u_l = tid>>4, b_l = tid&15. Accumulators are f32x2 over (even k,
// odd k); halves summed at the end of the k loop.
__global__ __launch_bounds__(TPB, 1) void lstm_recur(const float* __restrict__ R)
{
    extern __shared__ float sm[];
    float* R4  = sm + SM_R4;
    float* h4  = sm + SM_H4;
    float* xzs = sm + SM_XZ;

    const int tid = threadIdx.x;
    const int ug = blockIdx.x >> 2, bg = blockIdx.x & 3;
    const int u0 = ug * 16, b0 = bg * 16;
    const int b_l = tid & 15, u_l = tid >> 4;

    // ---- load R slice into SMEM: R4[kq][u][g*4+kl] = R[(kq*4+kl)][g*512+u0+u]
    for (int i = tid; i < 32768; i += TPB) {
        int kq = i >> 8, u = (i >> 4) & 15, e = i & 15, g = e >> 2, kl = e & 3;
        R4[i] = R[(size_t)(kq * 4 + kl) * FOURU + g * UNITS + u0 + u];
    }

    // ---- xz tile staging mapping: thread -> (pb, pg, pq)
    const int pb = tid >> 4, pg = (tid >> 2) & 3, pq = tid & 3;
    const float* xz_thread = g_xz + (size_t)(b0 + pb) * TSTEPS * FOURU
                             + pg * UNITS + u0 + pq * 4;

    // stage xz(t=0) into buffer 0
    {
        float4 v = __ldcs((const float4*)xz_thread);
        float vv[4] = {v.x, v.y, v.z, v.w};
#pragma unroll
        for (int j = 0; j < 4; j++)
            xzs[pg * 256 + (pq * 4 + j) * 16 + pb] = vv[j];
    }
    __syncthreads();

    unsigned* arrive = &g_arrive[bg * 32];
    volatile unsigned* gen = &g_gen[bg * 32];

    float c_state = 0.f;

    for (int t = 0; t < TSTEPS; t++) {
        // ---- prefetch xz(t+1) into registers (independent of h)
        float4 xnext = make_float4(0.f, 0.f, 0.f, 0.f);
        if (t + 1 < TSTEPS)
            xnext = __ldcs((const float4*)(xz_thread + (size_t)(t + 1) * FOURU));

        // ---- stage h(t) into SMEM: h4[k>>2][b][k&3]
        {
            const float* hsrc = &g_h[t & 1][0][0];
#pragma unroll
            for (int r = 0; r < 8; r++) {
                int i = r * TPB + tid;
                int k = i >> 2, bq = i & 3;
                float4 hv = __ldcg((const float4*)(hsrc + k * BATCH + b0 + bq * 4));
                float vv[4] = {hv.x, hv.y, hv.z, hv.w};
                int base = (k >> 2) * 64 + (k & 3);
#pragma unroll
                for (int j = 0; j < 4; j++)
                    h4[base + (bq * 4 + j) * 4] = vv[j];
            }
        }
        __syncthreads();

        // ---- 4 gate dot-products over k (f32x2 SIMD over k pairs)
        u64t a0 = 0ull, a1 = 0ull, a2 = 0ull, a3 = 0ull;
        const float* hrow = h4 + b_l * 4;
        const float* rrow = R4 + u_l * 16;
#pragma unroll 8
        for (int kq = 0; kq < 128; kq++) {
            ulonglong2 hh = *(const ulonglong2*)(hrow + kq * 64);
            ulonglong2 r0 = *(const ulonglong2*)(rrow + kq * 256);
            ulonglong2 r1 = *(const ulonglong2*)(rrow + kq * 256 + 4);
            ulonglong2 r2 = *(const ulonglong2*)(rrow + kq * 256 + 8);
            ulonglong2 r3 = *(const ulonglong2*)(rrow + kq * 256 + 12);
            ffma2(a0, r0.x, hh.x); ffma2(a0, r0.y, hh.y);
            ffma2(a1, r1.x, hh.x); ffma2(a1, r1.y, hh.y);
            ffma2(a2, r2.x, hh.x); ffma2(a2, r2.y, hh.y);
            ffma2(a3, r3.x, hh.x); ffma2(a3, r3.y, hh.y);
        }

        // ---- gates + state update
        const float* xb = xzs + (t & 1) * 1024 + u_l * 16 + b_l;
        float2 p;
        p = unpack2(a0); float z1 = p.x + p.y + xb[0];
        p = unpack2(a1); float z2 = p.x + p.y + xb[256];
        p = unpack2(a2); float z3 = p.x + p.y + xb[512];
        p = unpack2(a3); float z4 = p.x + p.y + xb[768];

        float v1 = ftanh(z1);
        float v2 = fsig(z2);
        float v3 = fsig(z3);
        float v4 = fsig(z4);
        c_state = v1 * v2 + v3 * c_state;
        float hnew = v4 * ftanh(c_state);

        __stcg(&g_h[(t + 1) & 1][u0 + u_l][b0 + b_l], hnew);

        // ---- store prefetched xz(t+1) into the other buffer
        if (t + 1 < TSTEPS) {
            float vv[4] = {xnext.x, xnext.y, xnext.z, xnext.w};
            float* dst = xzs + ((t + 1) & 1) * 1024;
#pragma unroll
            for (int j = 0; j < 4; j++)
                dst[pg * 256 + (pq * 4 + j) * 16 + pb] = vv[j];
        }

        // ---- per-batch-group barrier (32 CTAs)
        __syncthreads();
        if (tid == 0) {
            __threadfence();
            unsigned prev = atomicAdd(arrive, 1u);
            if (prev == GROUP_CTAS - 1) {
                atomicExch(arrive, 0u);
                __threadfence();
                *gen = (unsigned)(t + 1);
            } else {
                while (*gen < (unsigned)(t + 1)) { }
            }
            __threadfence();
        }
        __syncthreads();
    }
}

// -------- final dense + softmax: one warp per batch -------------------------
__global__ void fc_softmax(const float* __restrict__ fc_w,
                           const float* __restrict__ fc_b,
                           float* __restrict__ out)
{
    const int b = blockIdx.x;
    const int l = threadIdx.x;   // 32 threads
    float a0 = 0.f, a1 = 0.f, a2 = 0.f, a3 = 0.f;
    for (int k = l; k < UNITS; k += 32) {
        float h = g_h[0][k][b];   // t=1023 wrote buffer (1023+1)&1 = 0
        const float4 wv = *(const float4*)&fc_w[k * 4];
        a0 += h * wv.x; a1 += h * wv.y; a2 += h * wv.z; a3 += h * wv.w;
    }
#pragma unroll
    for (int o = 16; o > 0; o >>= 1) {
        a0 += __shfl_down_sync(0xffffffffu, a0, o);
        a1 += __shfl_down_sync(0xffffffffu, a1, o);
        a2 += __shfl_down_sync(0xffffffffu, a2, o);
        a3 += __shfl_down_sync(0xffffffffu, a3, o);
    }
    if (l == 0) {
        float z0 = a0 + fc_b[0], z1 = a1 + fc_b[1];
        float z2 = a2 + fc_b[2], z3 = a3 + fc_b[3];
        float m = fmaxf(fmaxf(z0, z1), fmaxf(z2, z3));
        float e0 = __expf(z0 - m), e1 = __expf(z1 - m);
        float e2 = __expf(z2 - m), e3 = __expf(z3 - m);
        float inv = __fdividef(1.f, e0 + e1 + e2 + e3);
        out[b * 4 + 0] = e0 * inv;
        out[b * 4 + 1] = e1 * inv;
        out[b * 4 + 2] = e2 * inv;
        out[b * 4 + 3] = e3 * inv;
    }
}

// ---------------------------------------------------------------------------
extern "C" void kernel_launch(void* const* d_in, const int* in_sizes, int n_in,
                              void* d_out, int out_size)
{
    const float* tx      = (const float*)d_in[0];  // [64,1024,512]
    const float* kernelW = (const float*)d_in[1];  // [512,2048]
    const float* R       = (const float*)d_in[2];  // [512,2048]
    const float* bias    = (const float*)d_in[3];  // [2048]
    const float* fc_w    = (const float*)d_in[4];  // [512,4]
    const float* fc_b    = (const float*)d_in[5];  // [4]
    float* out           = (float*)d_out;          // [64,4]

    cudaFuncSetAttribute(lstm_recur,
                         cudaFuncAttributeMaxDynamicSharedMemorySize, SM_BYTES);

    init_kernel<<<(2 * UNITS * BATCH + 255) / 256, 256>>>();
    sgemm_bias<<<dim3(FOURU / 128, (BATCH * TSTEPS) / 128), 256>>>(tx, kernelW, bias);
    lstm_recur<<<NCTA, TPB, SM_BYTES>>>(R);
    fc_softmax<<<BATCH, 32>>>(fc_w, fc_b, out);
    (void)in_sizes; (void)n_in; (void)out_size;
}

// round 4
// speedup vs baseline: 1.7054x; 1.0005x over previous
#include <cuda_runtime.h>
#include <cstdint>

// ---------------------------------------------------------------------------
// Network_28054726377822 : LSTM  B=64, T=1024, D=512, U=512, OUT=4
//  1) xz = tx @ kernel + bias              (f32x2 SGEMM)
//  2) 1024 sequential steps, persistent kernel, 128 CTAs:
//       CTA = (unit-group of 16) x (batch-group of 16)
//       R slice in SMEM (128 KB), h staged via SMEM, f32x2 SIMD over k,
//       per-batch-group grid barrier (4 groups x 32 CTAs)
//  3) out = softmax(h_last @ fc_w + fc_b)
// ---------------------------------------------------------------------------

#define BATCH    64
#define TSTEPS   1024
#define DIN      512
#define UNITS    512
#define FOURU    2048
#define NCTA     128
#define TPB      256
#define NBG      4
#define GROUP_CTAS 32

// smem layout (floats)
#define SM_R4    0          // [128 kq][16 u][16 e]   e = g*4+kl : 32768
#define SM_H4    32768      // [128 kq][16 b][4 kl]              : 8192
#define SM_XZ    40960      // [2 buf][4 g][16 u][16 b]          : 2048
#define SM_FLOATS 43008
#define SM_BYTES (SM_FLOATS * 4)

// -------- device scratch ----------------------------------------------------
__device__ float             g_xz[(size_t)BATCH * TSTEPS * FOURU];  // 512 MB
__device__ float             g_h[2][UNITS][BATCH];                  // hT[par][k][b]
__device__ unsigned          g_arrive[NBG * 32];                    // padded
__device__ volatile unsigned g_gen[NBG * 32];                       // padded

// -------- packed f32x2 helpers ---------------------------------------------
typedef unsigned long long u64t;
__device__ __forceinline__ u64t splat2(float x) {
    u64t r; asm("mov.b64 %0, {%1, %1};" : "=l"(r) : "f"(x)); return r;
}
__device__ __forceinline__ void ffma2(u64t& d, u64t a, u64t b) {
    asm("fma.rn.f32x2 %0, %1, %2, %0;" : "+l"(d) : "l"(a), "l"(b));
}
__device__ __forceinline__ float2 unpack2(u64t v) {
    float2 f; asm("mov.b64 {%0, %1}, %2;" : "=f"(f.x), "=f"(f.y) : "l"(v)); return f;
}
__device__ __forceinline__ float fsig(float x) {
    return __fdividef(1.f, 1.f + __expf(-x));
}
__device__ __forceinline__ float ftanh(float x) {
    return 1.f - __fdividef(2.f, __expf(2.f * x) + 1.f);
}

// -------- init --------------------------------------------------------------
__global__ void init_kernel() {
    int i = blockIdx.x * blockDim.x + threadIdx.x;
    if (i < 2 * UNITS * BATCH) ((float*)g_h)[i] = 0.f;
    if (i < NBG * 32) { g_arrive[i] = 0u; g_gen[i] = 0u; }
}

// -------- input GEMM: g_xz[65536,2048] = A[65536,512] @ W[512,2048] + bias --
__global__ __launch_bounds__(256) void sgemm_bias(
    const float* __restrict__ A, const float* __restrict__ W,
    const float* __restrict__ bias)
{
    __shared__ float As[8][128];
    __shared__ float Bs[8][128];

    const int tid = threadIdx.x;
    const int tx = tid & 15, ty = tid >> 4;
    const int bx = blockIdx.x, by = blockIdx.y;

    const int aRow = tid >> 1, aK = (tid & 1) * 4;
    const int wK = tid >> 5, wN = (tid & 31) * 4;

    const float* Aptr = A + (size_t)(by * 128 + aRow) * DIN + aK;
    const float* Wptr = W + (size_t)wK * FOURU + bx * 128 + wN;

    float4 aReg = *(const float4*)Aptr;
    float4 wReg = *(const float4*)Wptr;

    u64t acc[8][4];
#pragma unroll
    for (int m = 0; m < 8; m++)
#pragma unroll
        for (int n = 0; n < 4; n++) acc[m][n] = 0ull;

    for (int kt = 0; kt < DIN / 8; kt++) {
        As[aK + 0][aRow] = aReg.x;
        As[aK + 1][aRow] = aReg.y;
        As[aK + 2][aRow] = aReg.z;
        As[aK + 3][aRow] = aReg.w;
        *(float4*)&Bs[wK][wN] = wReg;
        __syncthreads();

        if (kt < DIN / 8 - 1) {
            aReg = *(const float4*)(Aptr + (kt + 1) * 8);
            wReg = *(const float4*)(Wptr + (size_t)(kt + 1) * 8 * FOURU);
        }

#pragma unroll
        for (int k = 0; k < 8; k++) {
            float4 a0 = *(const float4*)&As[k][ty * 8];
            float4 a1 = *(const float4*)&As[k][ty * 8 + 4];
            ulonglong2 b01 = *(const ulonglong2*)&Bs[k][tx * 8];
            ulonglong2 b23 = *(const ulonglong2*)&Bs[k][tx * 8 + 4];
            float av[8] = {a0.x, a0.y, a0.z, a0.w, a1.x, a1.y, a1.z, a1.w};
#pragma unroll
            for (int m = 0; m < 8; m++) {
                u64t s = splat2(av[m]);
                ffma2(acc[m][0], b01.x, s);
                ffma2(acc[m][1], b01.y, s);
                ffma2(acc[m][2], b23.x, s);
                ffma2(acc[m][3], b23.y, s);
            }
        }
        __syncthreads();
    }

    float4 bias0 = *(const float4*)&bias[bx * 128 + tx * 8];
    float4 bias1 = *(const float4*)&bias[bx * 128 + tx * 8 + 4];
#pragma unroll
    for (int m = 0; m < 8; m++) {
        float* Cp = g_xz + (size_t)(by * 128 + ty * 8 + m) * FOURU + bx * 128 + tx * 8;
        float2 p0 = unpack2(acc[m][0]);
        float2 p1 = unpack2(acc[m][1]);
        float2 p2 = unpack2(acc[m][2]);
        float2 p3 = unpack2(acc[m][3]);
        float4 o0 = make_float4(p0.x + bias0.x, p0.y + bias0.y,
                                p1.x + bias0.z, p1.y + bias0.w);
        float4 o1 = make_float4(p2.x + bias1.x, p2.y + bias1.y,
                                p3.x + bias1.z, p3.y + bias1.w);
        __stcs((float4*)Cp, o0);            // streaming: xz read exactly once later
        __stcs((float4*)(Cp + 4), o1);
    }
}

// -------- persistent LSTM recurrence ---------------------------------------
// CTA (ug, bg): units [16*ug, 16*ug+16), batches [16*bg, 16*bg+16).
// Thread: u_l = tid>>4, b_l = tid&15. Accumulators are f32x2 over (even k,
// odd k); halves summed at the end of the k loop.
__global__ __launch_bounds__(TPB, 1) void lstm_recur(const float* __restrict__ R)
{
    extern __shared__ float sm[];
    float* R4  = sm + SM_R4;
    float* h4  = sm + SM_H4;
    float* xzs = sm + SM_XZ;

    const int tid = threadIdx.x;
    const int ug = blockIdx.x >> 2, bg = blockIdx.x & 3;
    const int u0 = ug * 16, b0 = bg * 16;
    const int b_l = tid & 15, u_l = tid >> 4;

    // ---- load R slice into SMEM: R4[kq][u][g*4+kl] = R[(kq*4+kl)][g*512+u0+u]
    for (int i = tid; i < 32768; i += TPB) {
        int kq = i >> 8, u = (i >> 4) & 15, e = i & 15, g = e >> 2, kl = e & 3;
        R4[i] = R[(size_t)(kq * 4 + kl) * FOURU + g * UNITS + u0 + u];
    }

    // ---- xz tile staging mapping: thread -> (pb, pg, pq)
    const int pb = tid >> 4, pg = (tid >> 2) & 3, pq = tid & 3;
    const float* xz_thread = g_xz + (size_t)(b0 + pb) * TSTEPS * FOURU
                             + pg * UNITS + u0 + pq * 4;

    // stage xz(t=0) into buffer 0
    {
        float4 v = __ldcs((const float4*)xz_thread);
        float vv[4] = {v.x, v.y, v.z, v.w};
#pragma unroll
        for (int j = 0; j < 4; j++)
            xzs[pg * 256 + (pq * 4 + j) * 16 + pb] = vv[j];
    }
    __syncthreads();

    unsigned* arrive = &g_arrive[bg * 32];
    volatile unsigned* gen = &g_gen[bg * 32];

    float c_state = 0.f;

    for (int t = 0; t < TSTEPS; t++) {
        // ---- prefetch xz(t+1) into registers (independent of h)
        float4 xnext = make_float4(0.f, 0.f, 0.f, 0.f);
        if (t + 1 < TSTEPS)
            xnext = __ldcs((const float4*)(xz_thread + (size_t)(t + 1) * FOURU));

        // ---- stage h(t) into SMEM: h4[k>>2][b][k&3]
        {
            const float* hsrc = &g_h[t & 1][0][0];
#pragma unroll
            for (int r = 0; r < 8; r++) {
                int i = r * TPB + tid;
                int k = i >> 2, bq = i & 3;
                float4 hv = __ldcg((const float4*)(hsrc + k * BATCH + b0 + bq * 4));
                float vv[4] = {hv.x, hv.y, hv.z, hv.w};
                int base = (k >> 2) * 64 + (k & 3);
#pragma unroll
                for (int j = 0; j < 4; j++)
                    h4[base + (bq * 4 + j) * 4] = vv[j];
            }
        }
        __syncthreads();

        // ---- 4 gate dot-products over k (f32x2 SIMD over k pairs)
        u64t a0 = 0ull, a1 = 0ull, a2 = 0ull, a3 = 0ull;
        const float* hrow = h4 + b_l * 4;
        const float* rrow = R4 + u_l * 16;
#pragma unroll 8
        for (int kq = 0; kq < 128; kq++) {
            ulonglong2 hh = *(const ulonglong2*)(hrow + kq * 64);
            ulonglong2 r0 = *(const ulonglong2*)(rrow + kq * 256);
            ulonglong2 r1 = *(const ulonglong2*)(rrow + kq * 256 + 4);
            ulonglong2 r2 = *(const ulonglong2*)(rrow + kq * 256 + 8);
            ulonglong2 r3 = *(const ulonglong2*)(rrow + kq * 256 + 12);
            ffma2(a0, r0.x, hh.x); ffma2(a0, r0.y, hh.y);
            ffma2(a1, r1.x, hh.x); ffma2(a1, r1.y, hh.y);
            ffma2(a2, r2.x, hh.x); ffma2(a2, r2.y, hh.y);
            ffma2(a3, r3.x, hh.x); ffma2(a3, r3.y, hh.y);
        }

        // ---- gates + state update
        const float* xb = xzs + (t & 1) * 1024 + u_l * 16 + b_l;
        float2 p;
        p = unpack2(a0); float z1 = p.x + p.y + xb[0];
        p = unpack2(a1); float z2 = p.x + p.y + xb[256];
        p = unpack2(a2); float z3 = p.x + p.y + xb[512];
        p = unpack2(a3); float z4 = p.x + p.y + xb[768];

        float v1 = ftanh(z1);
        float v2 = fsig(z2);
        float v3 = fsig(z3);
        float v4 = fsig(z4);
        c_state = v1 * v2 + v3 * c_state;
        float hnew = v4 * ftanh(c_state);

        __stcg(&g_h[(t + 1) & 1][u0 + u_l][b0 + b_l], hnew);

        // ---- store prefetched xz(t+1) into the other buffer
        if (t + 1 < TSTEPS) {
            float vv[4] = {xnext.x, xnext.y, xnext.z, xnext.w};
            float* dst = xzs + ((t + 1) & 1) * 1024;
#pragma unroll
            for (int j = 0; j < 4; j++)
                dst[pg * 256 + (pq * 4 + j) * 16 + pb] = vv[j];
        }

        // ---- per-batch-group barrier (32 CTAs)
        __syncthreads();
        if (tid == 0) {
            __threadfence();
            unsigned prev = atomicAdd(arrive, 1u);
            if (prev == GROUP_CTAS - 1) {
                atomicExch(arrive, 0u);
                __threadfence();
                *gen = (unsigned)(t + 1);
            } else {
                while (*gen < (unsigned)(t + 1)) { }
            }
            __threadfence();
        }
        __syncthreads();
    }
}

// -------- final dense + softmax: one warp per batch -------------------------
__global__ void fc_softmax(const float* __restrict__ fc_w,
                           const float* __restrict__ fc_b,
                           float* __restrict__ out)
{
    const int b = blockIdx.x;
    const int l = threadIdx.x;   // 32 threads
    float a0 = 0.f, a1 = 0.f, a2 = 0.f, a3 = 0.f;
    for (int k = l; k < UNITS; k += 32) {
        float h = g_h[0][k][b];   // t=1023 wrote buffer (1023+1)&1 = 0
        const float4 wv = *(const float4*)&fc_w[k * 4];
        a0 += h * wv.x; a1 += h * wv.y; a2 += h * wv.z; a3 += h * wv.w;
    }
#pragma unroll
    for (int o = 16; o > 0; o >>= 1) {
        a0 += __shfl_down_sync(0xffffffffu, a0, o);
        a1 += __shfl_down_sync(0xffffffffu, a1, o);
        a2 += __shfl_down_sync(0xffffffffu, a2, o);
        a3 += __shfl_down_sync(0xffffffffu, a3, o);
    }
    if (l == 0) {
        float z0 = a0 + fc_b[0], z1 = a1 + fc_b[1];
        float z2 = a2 + fc_b[2], z3 = a3 + fc_b[3];
        float m = fmaxf(fmaxf(z0, z1), fmaxf(z2, z3));
        float e0 = __expf(z0 - m), e1 = __expf(z1 - m);
        float e2 = __expf(z2 - m), e3 = __expf(z3 - m);
        float inv = __fdividef(1.f, e0 + e1 + e2 + e3);
        out[b * 4 + 0] = e0 * inv;
        out[b * 4 + 1] = e1 * inv;
        out[b * 4 + 2] = e2 * inv;
        out[b * 4 + 3] = e3 * inv;
    }
}

// ---------------------------------------------------------------------------
extern "C" void kernel_launch(void* const* d_in, const int* in_sizes, int n_in,
                              void* d_out, int out_size)
{
    const float* tx      = (const float*)d_in[0];  // [64,1024,512]
    const float* kernelW = (const float*)d_in[1];  // [512,2048]
    const float* R       = (const float*)d_in[2];  // [512,2048]
    const float* bias    = (const float*)d_in[3];  // [2048]
    const float* fc_w    = (const float*)d_in[4];  // [512,4]
    const float* fc_b    = (const float*)d_in[5];  // [4]
    float* out           = (float*)d_out;          // [64,4]

    cudaFuncSetAttribute(lstm_recur,
                         cudaFuncAttributeMaxDynamicSharedMemorySize, SM_BYTES);

    init_kernel<<<(2 * UNITS * BATCH + 255) / 256, 256>>>();
    sgemm_bias<<<dim3(FOURU / 128, (BATCH * TSTEPS) / 128), 256>>>(tx, kernelW, bias);
    lstm_recur<<<NCTA, TPB, SM_BYTES>>>(R);
    fc_softmax<<<BATCH, 32>>>(fc_w, fc_b, out);
    (void)in_sizes; (void)n_in; (void)out_size;
}